// round 5
// baseline (speedup 1.0000x reference)
#include <cuda_runtime.h>
#include <cstdint>

// Problem shape (fixed)
#define BATCH 64
#define TT    2048
#define DD    256
#define HH    256

// Packed fp32x2 ops (sm_100+ PTX; ptxas never emits these from C++)
#define FMA2(acc, a, b) \
    asm("fma.rn.f32x2 %0, %1, %2, %0;" : "+l"(acc) : "l"(a), "l"(b))
#define SPLAT2(dst, s) \
    asm("mov.b64 %0, {%1, %1};" : "=l"(dst) : "f"(s))
#define PACK2(dst, lo, hi) \
    asm("mov.b64 %0, {%1, %2};" : "=l"(dst) : "f"(lo), "f"(hi))
#define UNPACK2(lo, hi, src) \
    asm("mov.b64 {%0, %1}, %2;" : "=f"(lo), "=f"(hi) : "l"(src))

// ---------------------------------------------------------------------------
// Kernel A: xp = x @ Wxh + bias   (M=B*T, K=D, N=H), f32x2 inner product
// BM=128, BN=128, BK=8, 256 threads, 8x8 micro-tile (as 8x4 f32x2 pairs)
// ---------------------------------------------------------------------------
#define BM 128
#define BN 128
#define BK 8
#define TM 8
#define TN 8

__global__ __launch_bounds__(256) void xp_gemm_kernel(
    const float* __restrict__ X,
    const float* __restrict__ W,
    const float* __restrict__ bias,
    float* __restrict__ out)
{
    __shared__ float As[BK][BM];
    __shared__ __align__(16) float Bs[BK][BN];

    const int m0 = blockIdx.x * BM;
    const int n0 = blockIdx.y * BN;
    const int tid = threadIdx.x;
    const int tx = tid & 15;   // N
    const int ty = tid >> 4;   // M

    const int a_r = tid >> 1;
    const int a_k = (tid & 1) * 4;
    const int b_r = tid >> 5;
    const int b_n = (tid & 31) * 4;

    unsigned long long acc[TM][TN / 2];
#pragma unroll
    for (int i = 0; i < TM; i++)
#pragma unroll
        for (int j = 0; j < TN / 2; j++) acc[i][j] = 0ull;

    const float* Xp = X + (long long)m0 * DD;

    for (int k0 = 0; k0 < DD; k0 += BK) {
        float4 av = *reinterpret_cast<const float4*>(Xp + (long long)a_r * DD + k0 + a_k);
        As[a_k + 0][a_r] = av.x;
        As[a_k + 1][a_r] = av.y;
        As[a_k + 2][a_r] = av.z;
        As[a_k + 3][a_r] = av.w;
        float4 bv = *reinterpret_cast<const float4*>(W + (long long)(k0 + b_r) * HH + n0 + b_n);
        *reinterpret_cast<float4*>(&Bs[b_r][b_n]) = bv;
        __syncthreads();

#pragma unroll
        for (int k = 0; k < BK; k++) {
            ulonglong2 b01 = *reinterpret_cast<const ulonglong2*>(&Bs[k][tx * TN]);
            ulonglong2 b23 = *reinterpret_cast<const ulonglong2*>(&Bs[k][tx * TN + 4]);
            float ar[TM];
#pragma unroll
            for (int i = 0; i < TM; i++) ar[i] = As[k][ty * TM + i];
#pragma unroll
            for (int i = 0; i < TM; i++) {
                unsigned long long ai;
                SPLAT2(ai, ar[i]);
                FMA2(acc[i][0], ai, b01.x);
                FMA2(acc[i][1], ai, b01.y);
                FMA2(acc[i][2], ai, b23.x);
                FMA2(acc[i][3], ai, b23.y);
            }
        }
        __syncthreads();
    }

    float bv[TN];
#pragma unroll
    for (int j = 0; j < TN; j++) bv[j] = bias[n0 + tx * TN + j];

#pragma unroll
    for (int i = 0; i < TM; i++) {
        const int row = m0 + ty * TM + i;
        float* op = out + (long long)row * HH + n0 + tx * TN;
        float r[TN];
#pragma unroll
        for (int j = 0; j < TN / 2; j++) {
            UNPACK2(r[2 * j], r[2 * j + 1], acc[i][j]);
        }
        float4 r0, r1;
        r0.x = r[0] + bv[0]; r0.y = r[1] + bv[1];
        r0.z = r[2] + bv[2]; r0.w = r[3] + bv[3];
        r1.x = r[4] + bv[4]; r1.y = r[5] + bv[5];
        r1.z = r[6] + bv[6]; r1.w = r[7] + bv[7];
        *reinterpret_cast<float4*>(op)     = r0;
        *reinterpret_cast<float4*>(op + 4) = r1;
    }
}

// ---------------------------------------------------------------------------
// Kernel B: recurrence. One CTA per batch, 512 threads.
// 2-way K-split: thread (half, col) owns Whh rows [half*128, half*128+128)
// of column col, held entirely in registers as 64 f32x2 pairs (128 regs).
// Per step: each thread does a 128-long dot-product against its half of h,
// exchanges partials via smem, both halves compute tanh; half 0 writes h to
// the double-buffered smem h, half 1 writes h to gmem. Two barriers/step.
// ---------------------------------------------------------------------------
#define KSPLIT 2
#define ROWS_PER_TH (HH / KSPLIT)       // 128
#define WPAIRS (ROWS_PER_TH / 2)        // 64 f32x2 pairs = 128 regs

__global__ __launch_bounds__(512, 1) void rnn_rec_kernel(
    const float* __restrict__ Whh,
    float* __restrict__ out)
{
    __shared__ __align__(16) float hbuf[2][HH];     // double-buffered h
    __shared__ float part[KSPLIT][HH];              // partial dot-products

    const int tid  = threadIdx.x;
    const int col  = tid & (HH - 1);
    const int half = tid >> 8;          // 0 or 1
    const int b    = blockIdx.x;

    // one-time: register-resident Whh slice (rows [half*128, half*128+128))
    const int rbase = half * ROWS_PER_TH;
    unsigned long long wp[WPAIRS];
#pragma unroll
    for (int p = 0; p < WPAIRS; p++) {
        float w0 = Whh[(rbase + 2 * p + 0) * HH + col];
        float w1 = Whh[(rbase + 2 * p + 1) * HH + col];
        PACK2(wp[p], w0, w1);
    }

    if (half == 0) hbuf[0][col] = 0.f;
    __syncthreads();

    float* orow = out + (long long)b * TT * HH;
    float xpv = orow[col];              // xp at t=0 (both halves load; broadcast)

    int cur = 0;

#pragma unroll 1
    for (int t = 0; t < TT; t++) {
        float xnext = 0.f;
        if (t + 1 < TT) xnext = orow[(t + 1) * HH + col];

        const ulonglong2* h2 =
            reinterpret_cast<const ulonglong2*>(&hbuf[cur][rbase]);

        unsigned long long a0 = 0ull, a1 = 0ull, a2 = 0ull, a3 = 0ull;
#pragma unroll
        for (int j = 0; j < WPAIRS / 4; j++) {   // 16 iters: 2 LDS.128 + 4 FMA2
            ulonglong2 hA = h2[2 * j];
            ulonglong2 hB = h2[2 * j + 1];
            FMA2(a0, hA.x, wp[4 * j + 0]);
            FMA2(a1, hA.y, wp[4 * j + 1]);
            FMA2(a2, hB.x, wp[4 * j + 2]);
            FMA2(a3, hB.y, wp[4 * j + 3]);
        }

        float s0, s1, s2, s3, s4, s5, s6, s7;
        UNPACK2(s0, s1, a0);
        UNPACK2(s2, s3, a1);
        UNPACK2(s4, s5, a2);
        UNPACK2(s6, s7, a3);
        float s = ((s0 + s1) + (s2 + s3)) + ((s4 + s5) + (s6 + s7));

        part[half][col] = s;
        __syncthreads();

        float v = tanhf(xpv + part[0][col] + part[1][col]);

        if (half == 0) {
            hbuf[cur ^ 1][col] = v;     // h for next step
        } else {
            orow[t * HH + col] = v;     // h_t to gmem (overwrites xp slot)
        }
        __syncthreads();

        cur ^= 1;
        xpv = xnext;
    }
}

// ---------------------------------------------------------------------------
extern "C" void kernel_launch(void* const* d_in, const int* in_sizes, int n_in,
                              void* d_out, int out_size)
{
    const float* x    = (const float*)d_in[0];
    const float* Wxh  = (const float*)d_in[1];
    const float* Whh  = (const float*)d_in[2];
    const float* bias = (const float*)d_in[3];
    float* out = (float*)d_out;

    const int M = in_sizes[0] / DD;   // B*T

    dim3 gridA(M / BM, HH / BN);
    xp_gemm_kernel<<<gridA, 256>>>(x, Wxh, bias, out);

    rnn_rec_kernel<<<BATCH, 512>>>(Whh, out);
}

// round 7
// speedup vs baseline: 1.4536x; 1.4536x over previous
#include <cuda_runtime.h>
#include <cstdint>

// Problem shape (fixed)
#define BATCH 64
#define TT    2048
#define DD    256
#define HH    256

// Packed fp32x2 ops (sm_100+ PTX; ptxas never emits these from C++)
#define FMA2(acc, a, b) \
    asm("fma.rn.f32x2 %0, %1, %2, %0;" : "+l"(acc) : "l"(a), "l"(b))
#define SPLAT2(dst, s) \
    asm("mov.b64 %0, {%1, %1};" : "=l"(dst) : "f"(s))
#define PACK2(dst, lo, hi) \
    asm("mov.b64 %0, {%1, %2};" : "=l"(dst) : "f"(lo), "f"(hi))
#define UNPACK2(lo, hi, src) \
    asm("mov.b64 {%0, %1}, %2;" : "=f"(lo), "=f"(hi) : "l"(src))

__device__ __forceinline__ uint32_t smem_u32(const void* p) {
    uint32_t a;
    asm("{ .reg .u64 t; cvta.to.shared.u64 t, %1; cvt.u32.u64 %0, t; }"
        : "=r"(a) : "l"(p));
    return a;
}

// ---------------------------------------------------------------------------
// Kernel A: xp = x @ Wxh + bias   (M=B*T, K=D, N=H), f32x2 inner product
// BM=128, BN=128, BK=8, 256 threads, 8x8 micro-tile (as 8x4 f32x2 pairs)
// ---------------------------------------------------------------------------
#define BM 128
#define BN 128
#define BK 8
#define TM 8
#define TN 8

__global__ __launch_bounds__(256) void xp_gemm_kernel(
    const float* __restrict__ X,
    const float* __restrict__ W,
    const float* __restrict__ bias,
    float* __restrict__ out)
{
    __shared__ float As[BK][BM];
    __shared__ __align__(16) float Bs[BK][BN];

    const int m0 = blockIdx.x * BM;
    const int n0 = blockIdx.y * BN;
    const int tid = threadIdx.x;
    const int tx = tid & 15;   // N
    const int ty = tid >> 4;   // M

    const int a_r = tid >> 1;
    const int a_k = (tid & 1) * 4;
    const int b_r = tid >> 5;
    const int b_n = (tid & 31) * 4;

    unsigned long long acc[TM][TN / 2];
#pragma unroll
    for (int i = 0; i < TM; i++)
#pragma unroll
        for (int j = 0; j < TN / 2; j++) acc[i][j] = 0ull;

    const float* Xp = X + (long long)m0 * DD;

    for (int k0 = 0; k0 < DD; k0 += BK) {
        float4 av = *reinterpret_cast<const float4*>(Xp + (long long)a_r * DD + k0 + a_k);
        As[a_k + 0][a_r] = av.x;
        As[a_k + 1][a_r] = av.y;
        As[a_k + 2][a_r] = av.z;
        As[a_k + 3][a_r] = av.w;
        float4 bv = *reinterpret_cast<const float4*>(W + (long long)(k0 + b_r) * HH + n0 + b_n);
        *reinterpret_cast<float4*>(&Bs[b_r][b_n]) = bv;
        __syncthreads();

#pragma unroll
        for (int k = 0; k < BK; k++) {
            ulonglong2 b01 = *reinterpret_cast<const ulonglong2*>(&Bs[k][tx * TN]);
            ulonglong2 b23 = *reinterpret_cast<const ulonglong2*>(&Bs[k][tx * TN + 4]);
            float ar[TM];
#pragma unroll
            for (int i = 0; i < TM; i++) ar[i] = As[k][ty * TM + i];
#pragma unroll
            for (int i = 0; i < TM; i++) {
                unsigned long long ai;
                SPLAT2(ai, ar[i]);
                FMA2(acc[i][0], ai, b01.x);
                FMA2(acc[i][1], ai, b01.y);
                FMA2(acc[i][2], ai, b23.x);
                FMA2(acc[i][3], ai, b23.y);
            }
        }
        __syncthreads();
    }

    float bv[TN];
#pragma unroll
    for (int j = 0; j < TN; j++) bv[j] = bias[n0 + tx * TN + j];

#pragma unroll
    for (int i = 0; i < TM; i++) {
        const int row = m0 + ty * TM + i;
        float* op = out + (long long)row * HH + n0 + tx * TN;
        float r[TN];
#pragma unroll
        for (int j = 0; j < TN / 2; j++) {
            UNPACK2(r[2 * j], r[2 * j + 1], acc[i][j]);
        }
        float4 r0, r1;
        r0.x = r[0] + bv[0]; r0.y = r[1] + bv[1];
        r0.z = r[2] + bv[2]; r0.w = r[3] + bv[3];
        r1.x = r[4] + bv[4]; r1.y = r[5] + bv[5];
        r1.z = r[6] + bv[6]; r1.w = r[7] + bv[7];
        *reinterpret_cast<float4*>(op)     = r0;
        *reinterpret_cast<float4*>(op + 4) = r1;
    }
}

// ---------------------------------------------------------------------------
// Kernel B: recurrence on a 2-CTA cluster per batch element.
//   cluster rank r owns output columns [r*128, (r+1)*128)
//   256 threads = (c = col_local 0..127) x (kh = k-half 0..1)
//   thread (c,kh) holds Whh[k][gcol] for k in [kh*128, kh*128+128)
//     -> 64 f32x2 pairs = 128 registers (budget 256: no spill)
// Per step:
//   partial_kh[c] = sum_k h[k] * W[k][gcol]     (h from local smem, full 256)
//   __syncthreads; v = tanh(xp + p0 + p1)       (both kh compute, redundant)
//   kh0: store v -> local hbuf[nxt][gcol], arrive local mbar
//   kh1: store v -> peer  hbuf[nxt][gcol] (DSMEM), arrive peer mbar
//        (release.cluster), store v -> gmem
//   all: wait local mbar (acquire.cluster), parity = t&1
// mbar count = 256 = 128 local kh0 arrives + 128 peer kh1 arrives.
// ---------------------------------------------------------------------------
#define KHALF_ROWS 128
#define WPAIRS (KHALF_ROWS / 2)    // 64 pairs = 128 regs

__global__ __launch_bounds__(256, 1) __cluster_dims__(2, 1, 1)
void rnn_rec_kernel(
    const float* __restrict__ Whh,
    float* __restrict__ out)
{
    __shared__ __align__(16) float hbuf[2][HH];   // full h, double-buffered
    __shared__ float part[2][KHALF_ROWS];
    __shared__ __align__(8) unsigned long long mbar;

    const int tid = threadIdx.x;
    const int c   = tid & 127;       // local column
    const int kh  = tid >> 7;        // k-half
    uint32_t rank;
    asm("mov.u32 %0, %%cluster_ctarank;" : "=r"(rank));
    const int batch = blockIdx.x >> 1;
    const int gcol  = (int)rank * 128 + c;

    // ---- one-time: register-resident Whh slice ----
    unsigned long long wp[WPAIRS];
#pragma unroll
    for (int p = 0; p < WPAIRS; p++) {
        float w0 = Whh[(kh * KHALF_ROWS + 2 * p + 0) * HH + gcol];
        float w1 = Whh[(kh * KHALF_ROWS + 2 * p + 1) * HH + gcol];
        PACK2(wp[p], w0, w1);
    }

    // init
    if (tid == 0) {
        uint32_t mb = smem_u32(&mbar);
        asm volatile("mbarrier.init.shared.b64 [%0], %1;" :: "r"(mb), "r"(256) : "memory");
    }
    hbuf[0][tid] = 0.f;              // 256 threads cover all 256 entries
    __syncthreads();
    // peer's mbar + hbuf must be initialized before any remote op
    asm volatile("barrier.cluster.arrive.aligned;" ::: "memory");
    asm volatile("barrier.cluster.wait.aligned;" ::: "memory");

    // precompute remote addresses (peer rank)
    const uint32_t mb_local  = smem_u32(&mbar);
    const uint32_t hb_local  = smem_u32(&hbuf[0][0]);
    uint32_t peer = rank ^ 1u;
    uint32_t mb_peer, hb_peer;
    asm("mapa.shared::cluster.u32 %0, %1, %2;" : "=r"(mb_peer) : "r"(mb_local), "r"(peer));
    asm("mapa.shared::cluster.u32 %0, %1, %2;" : "=r"(hb_peer) : "r"(hb_local), "r"(peer));

    float* orow = out + (long long)batch * TT * HH;
    float xpv = orow[gcol];
    int cur = 0;

#pragma unroll 1
    for (int t = 0; t < TT; t++) {
        float xnext = 0.f;
        if (t + 1 < TT) xnext = orow[(t + 1) * HH + gcol];

        // partial dot product over this thread's k-half
        const ulonglong2* h2 =
            reinterpret_cast<const ulonglong2*>(&hbuf[cur][kh * KHALF_ROWS]);
        unsigned long long a0 = 0ull, a1 = 0ull, a2 = 0ull, a3 = 0ull;
#pragma unroll
        for (int j = 0; j < WPAIRS / 4; j++) {   // 16 iters
            ulonglong2 hA = h2[2 * j];
            ulonglong2 hB = h2[2 * j + 1];
            FMA2(a0, hA.x, wp[4 * j + 0]);
            FMA2(a1, hA.y, wp[4 * j + 1]);
            FMA2(a2, hB.x, wp[4 * j + 2]);
            FMA2(a3, hB.y, wp[4 * j + 3]);
        }
        float s0, s1, s2, s3, s4, s5, s6, s7;
        UNPACK2(s0, s1, a0);
        UNPACK2(s2, s3, a1);
        UNPACK2(s4, s5, a2);
        UNPACK2(s6, s7, a3);
        part[kh][c] = ((s0 + s1) + (s2 + s3)) + ((s4 + s5) + (s6 + s7));
        __syncthreads();

        const int nxt = cur ^ 1;
        float v = tanhf(xpv + part[0][c] + part[1][c]);

        if (kh == 0) {
            hbuf[nxt][gcol] = v;
            // local arrive (release.cta is enough for local store/waiter pairs)
            asm volatile("mbarrier.arrive.shared.b64 _, [%0];"
                         :: "r"(mb_local) : "memory");
        } else {
            // DSMEM store of our columns into peer's next-h buffer
            uint32_t dst = hb_peer + (uint32_t)(nxt * HH + gcol) * 4u;
            asm volatile("st.shared::cluster.f32 [%0], %1;"
                         :: "r"(dst), "f"(v) : "memory");
            // release.cluster orders the DSMEM store before the remote arrive
            asm volatile("mbarrier.arrive.release.cluster.shared::cluster.b64 _, [%0];"
                         :: "r"(mb_peer) : "memory");
            orow[t * HH + gcol] = v;
        }

        // wait: 256 arrivals (128 local + 128 from peer), acquire.cluster
        {
            const uint32_t par = (uint32_t)(t & 1);
            uint32_t done;
            asm volatile(
                "{\n\t.reg .pred p;\n\t"
                "mbarrier.try_wait.parity.acquire.cluster.shared::cta.b64 p, [%1], %2;\n\t"
                "selp.b32 %0, 1, 0, p;\n\t}"
                : "=r"(done) : "r"(mb_local), "r"(par) : "memory");
            if (!done) {
                asm volatile(
                    "{\n\t.reg .pred P1;\n\t"
                    "WL_%=:\n\t"
                    "mbarrier.try_wait.parity.acquire.cluster.shared::cta.b64 P1, [%0], %1, 0x989680;\n\t"
                    "@P1 bra.uni WD_%=;\n\t"
                    "bra.uni WL_%=;\n\t"
                    "WD_%=:\n\t}"
                    :: "r"(mb_local), "r"(par) : "memory");
            }
        }

        cur = nxt;
        xpv = xnext;
    }

    // drain: no CTA exits while peer might still touch its smem
    asm volatile("barrier.cluster.arrive.aligned;" ::: "memory");
    asm volatile("barrier.cluster.wait.aligned;" ::: "memory");
}

// ---------------------------------------------------------------------------
extern "C" void kernel_launch(void* const* d_in, const int* in_sizes, int n_in,
                              void* d_out, int out_size)
{
    const float* x    = (const float*)d_in[0];
    const float* Wxh  = (const float*)d_in[1];
    const float* Whh  = (const float*)d_in[2];
    const float* bias = (const float*)d_in[3];
    float* out = (float*)d_out;

    const int M = in_sizes[0] / DD;   // B*T

    dim3 gridA(M / BM, HH / BN);
    xp_gemm_kernel<<<gridA, 256>>>(x, Wxh, bias, out);

    // 2 CTAs per batch, cluster dims baked into the kernel attribute
    rnn_rec_kernel<<<BATCH * 2, 256>>>(Whh, out);
}

// round 9
// speedup vs baseline: 1.6094x; 1.1072x over previous
#include <cuda_runtime.h>
#include <cstdint>

// Problem shape (fixed)
#define BATCH 64
#define TT    2048
#define DD    256
#define HH    256

// Packed fp32x2 ops (sm_100+ PTX; ptxas never emits these from C++)
#define FMA2(acc, a, b) \
    asm("fma.rn.f32x2 %0, %1, %2, %0;" : "+l"(acc) : "l"(a), "l"(b))
#define SPLAT2(dst, s) \
    asm("mov.b64 %0, {%1, %1};" : "=l"(dst) : "f"(s))
#define PACK2(dst, lo, hi) \
    asm("mov.b64 %0, {%1, %2};" : "=l"(dst) : "f"(lo), "f"(hi))
#define UNPACK2(lo, hi, src) \
    asm("mov.b64 {%0, %1}, %2;" : "=f"(lo), "=f"(hi) : "l"(src))

__device__ __forceinline__ uint32_t smem_u32(const void* p) {
    uint32_t a;
    asm("{ .reg .u64 t; cvta.to.shared.u64 t, %1; cvt.u32.u64 %0, t; }"
        : "=r"(a) : "l"(p));
    return a;
}

// ---------------------------------------------------------------------------
// Kernel A: xp = x @ Wxh + bias   (M=B*T, K=D, N=H), f32x2 inner product
// ---------------------------------------------------------------------------
#define BM 128
#define BN 128
#define BK 8
#define TM 8
#define TN 8

__global__ __launch_bounds__(256) void xp_gemm_kernel(
    const float* __restrict__ X,
    const float* __restrict__ W,
    const float* __restrict__ bias,
    float* __restrict__ out)
{
    __shared__ float As[BK][BM];
    __shared__ __align__(16) float Bs[BK][BN];

    const int m0 = blockIdx.x * BM;
    const int n0 = blockIdx.y * BN;
    const int tid = threadIdx.x;
    const int tx = tid & 15;   // N
    const int ty = tid >> 4;   // M

    const int a_r = tid >> 1;
    const int a_k = (tid & 1) * 4;
    const int b_r = tid >> 5;
    const int b_n = (tid & 31) * 4;

    unsigned long long acc[TM][TN / 2];
#pragma unroll
    for (int i = 0; i < TM; i++)
#pragma unroll
        for (int j = 0; j < TN / 2; j++) acc[i][j] = 0ull;

    const float* Xp = X + (long long)m0 * DD;

    for (int k0 = 0; k0 < DD; k0 += BK) {
        float4 av = *reinterpret_cast<const float4*>(Xp + (long long)a_r * DD + k0 + a_k);
        As[a_k + 0][a_r] = av.x;
        As[a_k + 1][a_r] = av.y;
        As[a_k + 2][a_r] = av.z;
        As[a_k + 3][a_r] = av.w;
        float4 bv = *reinterpret_cast<const float4*>(W + (long long)(k0 + b_r) * HH + n0 + b_n);
        *reinterpret_cast<float4*>(&Bs[b_r][b_n]) = bv;
        __syncthreads();

#pragma unroll
        for (int k = 0; k < BK; k++) {
            ulonglong2 b01 = *reinterpret_cast<const ulonglong2*>(&Bs[k][tx * TN]);
            ulonglong2 b23 = *reinterpret_cast<const ulonglong2*>(&Bs[k][tx * TN + 4]);
            float ar[TM];
#pragma unroll
            for (int i = 0; i < TM; i++) ar[i] = As[k][ty * TM + i];
#pragma unroll
            for (int i = 0; i < TM; i++) {
                unsigned long long ai;
                SPLAT2(ai, ar[i]);
                FMA2(acc[i][0], ai, b01.x);
                FMA2(acc[i][1], ai, b01.y);
                FMA2(acc[i][2], ai, b23.x);
                FMA2(acc[i][3], ai, b23.y);
            }
        }
        __syncthreads();
    }

    float bv[TN];
#pragma unroll
    for (int j = 0; j < TN; j++) bv[j] = bias[n0 + tx * TN + j];

#pragma unroll
    for (int i = 0; i < TM; i++) {
        const int row = m0 + ty * TM + i;
        float* op = out + (long long)row * HH + n0 + tx * TN;
        float r[TN];
#pragma unroll
        for (int j = 0; j < TN / 2; j++) {
            UNPACK2(r[2 * j], r[2 * j + 1], acc[i][j]);
        }
        float4 r0, r1;
        r0.x = r[0] + bv[0]; r0.y = r[1] + bv[1];
        r0.z = r[2] + bv[2]; r0.w = r[3] + bv[3];
        r1.x = r[4] + bv[4]; r1.y = r[5] + bv[5];
        r1.z = r[6] + bv[6]; r1.w = r[7] + bv[7];
        *reinterpret_cast<float4*>(op)     = r0;
        *reinterpret_cast<float4*>(op + 4) = r1;
    }
}

// ---------------------------------------------------------------------------
// Kernel B: recurrence on a 2-CTA cluster per batch element, with the
// dot product split into a LOCAL-h phase (overlaps the peer's DSMEM flight)
// and a PEER-h phase (after the mbarrier wait).
//
//   cluster rank r owns output columns [r*128, (r+1)*128)
//   256 threads = (c = col 0..127) x (kh = 0..1)
//   thread (c,kh) weights:
//     Phase A: k in [rank*128 + kh*64, +64)   (local half of h)
//     Phase B: k in [peer*128 + kh*64, +64)   (peer half of h)
//   -> 64 f32x2 pairs = 128 weight registers.
//
// Per step:
//   A: acc over local half (no cluster wait needed)
//   wait mbar (128 peer arrivals), parity (t-1)&1; skipped at t=0
//   B: acc over peer half
//   part[kh][c] = accA + accB; __syncthreads (S1)
//   v = tanh(xp + part0 + part1)
//   kh0: v -> local hbuf[nxt]; kh1: v -> peer hbuf[nxt] (DSMEM) + arrive
//        peer mbar + v -> gmem
//   __syncthreads (S2)
// ---------------------------------------------------------------------------
#define QPAIRS 32   // 64 rows per phase -> 32 f32x2 pairs

__global__ __launch_bounds__(256, 1) __cluster_dims__(2, 1, 1)
void rnn_rec_kernel(
    const float* __restrict__ Whh,
    float* __restrict__ out)
{
    __shared__ __align__(16) float hbuf[2][HH];
    __shared__ float part[2][128];
    __shared__ __align__(8) unsigned long long mbar;

    const int tid = threadIdx.x;
    const int c   = tid & 127;
    const int kh  = tid >> 7;
    uint32_t rank;
    asm("mov.u32 %0, %%cluster_ctarank;" : "=r"(rank));
    const int batch = blockIdx.x >> 1;
    const int gcol  = (int)rank * 128 + c;

    const int kbaseA = (int)rank * 128 + kh * 64;         // local half slice
    const int kbaseB = (int)(rank ^ 1u) * 128 + kh * 64;  // peer half slice

    // ---- one-time: register-resident Whh slices ----
    unsigned long long wpA[QPAIRS], wpB[QPAIRS];
#pragma unroll
    for (int p = 0; p < QPAIRS; p++) {
        float a0 = Whh[(kbaseA + 2 * p + 0) * HH + gcol];
        float a1 = Whh[(kbaseA + 2 * p + 1) * HH + gcol];
        PACK2(wpA[p], a0, a1);
        float b0 = Whh[(kbaseB + 2 * p + 0) * HH + gcol];
        float b1 = Whh[(kbaseB + 2 * p + 1) * HH + gcol];
        PACK2(wpB[p], b0, b1);
    }

    if (tid == 0) {
        uint32_t mb = smem_u32(&mbar);
        asm volatile("mbarrier.init.shared.b64 [%0], %1;"
                     :: "r"(mb), "r"(128) : "memory");
    }
    hbuf[0][tid] = 0.f;
    __syncthreads();
    asm volatile("barrier.cluster.arrive.aligned;" ::: "memory");
    asm volatile("barrier.cluster.wait.aligned;" ::: "memory");

    const uint32_t mb_local = smem_u32(&mbar);
    const uint32_t hb_local = smem_u32(&hbuf[0][0]);
    uint32_t peer = rank ^ 1u;
    uint32_t mb_peer, hb_peer;
    asm("mapa.shared::cluster.u32 %0, %1, %2;" : "=r"(mb_peer) : "r"(mb_local), "r"(peer));
    asm("mapa.shared::cluster.u32 %0, %1, %2;" : "=r"(hb_peer) : "r"(hb_local), "r"(peer));

    float* orow = out + (long long)batch * TT * HH;
    float xpv = orow[gcol];
    int cur = 0;

#pragma unroll 1
    for (int t = 0; t < TT; t++) {
        float xnext = 0.f;
        if (t + 1 < TT) xnext = orow[(t + 1) * HH + gcol];

        unsigned long long a0 = 0ull, a1 = 0ull, a2 = 0ull, a3 = 0ull;

        // ---- Phase A: local half of h (ordered by S2 of previous step) ----
        {
            const ulonglong2* h2 =
                reinterpret_cast<const ulonglong2*>(&hbuf[cur][kbaseA]);
#pragma unroll
            for (int j = 0; j < QPAIRS / 4; j++) {   // 8 iters
                ulonglong2 hA = h2[2 * j];
                ulonglong2 hB = h2[2 * j + 1];
                FMA2(a0, hA.x, wpA[4 * j + 0]);
                FMA2(a1, hA.y, wpA[4 * j + 1]);
                FMA2(a2, hB.x, wpA[4 * j + 2]);
                FMA2(a3, hB.y, wpA[4 * j + 3]);
            }
        }

        // ---- Wait for peer half of h_t (skipped at t=0: h_0 fully local) ----
        if (t > 0) {
            const uint32_t par = (uint32_t)((t - 1) & 1);
            uint32_t done;
            asm volatile(
                "{\n\t.reg .pred p;\n\t"
                "mbarrier.try_wait.parity.acquire.cluster.shared::cta.b64 p, [%1], %2;\n\t"
                "selp.b32 %0, 1, 0, p;\n\t}"
                : "=r"(done) : "r"(mb_local), "r"(par) : "memory");
            if (!done) {
                asm volatile(
                    "{\n\t.reg .pred P1;\n\t"
                    "WL_%=:\n\t"
                    "mbarrier.try_wait.parity.acquire.cluster.shared::cta.b64 P1, [%0], %1, 0x989680;\n\t"
                    "@P1 bra.uni WD_%=;\n\t"
                    "bra.uni WL_%=;\n\t"
                    "WD_%=:\n\t}"
                    :: "r"(mb_local), "r"(par) : "memory");
            }
        }

        // ---- Phase B: peer half of h ----
        {
            const ulonglong2* h2 =
                reinterpret_cast<const ulonglong2*>(&hbuf[cur][kbaseB]);
#pragma unroll
            for (int j = 0; j < QPAIRS / 4; j++) {
                ulonglong2 hA = h2[2 * j];
                ulonglong2 hB = h2[2 * j + 1];
                FMA2(a0, hA.x, wpB[4 * j + 0]);
                FMA2(a1, hA.y, wpB[4 * j + 1]);
                FMA2(a2, hB.x, wpB[4 * j + 2]);
                FMA2(a3, hB.y, wpB[4 * j + 3]);
            }
        }

        float s0, s1, s2, s3, s4, s5, s6, s7;
        UNPACK2(s0, s1, a0);
        UNPACK2(s2, s3, a1);
        UNPACK2(s4, s5, a2);
        UNPACK2(s6, s7, a3);
        part[kh][c] = ((s0 + s1) + (s2 + s3)) + ((s4 + s5) + (s6 + s7));
        __syncthreads();                               // S1

        const int nxt = cur ^ 1;
        float v = tanhf(xpv + part[0][c] + part[1][c]);

        if (kh == 0) {
            hbuf[nxt][gcol] = v;                       // local half for t+1
        } else {
            if (t + 1 < TT) {
                uint32_t dst = hb_peer + (uint32_t)(nxt * HH + gcol) * 4u;
                asm volatile("st.shared::cluster.f32 [%0], %1;"
                             :: "r"(dst), "f"(v) : "memory");
                asm volatile("mbarrier.arrive.release.cluster.shared::cluster.b64 _, [%0];"
                             :: "r"(mb_peer) : "memory");
            }
            orow[t * HH + gcol] = v;                   // h_t to gmem
        }
        __syncthreads();                               // S2

        cur = nxt;
        xpv = xnext;
    }

    asm volatile("barrier.cluster.arrive.aligned;" ::: "memory");
    asm volatile("barrier.cluster.wait.aligned;" ::: "memory");
}

// ---------------------------------------------------------------------------
extern "C" void kernel_launch(void* const* d_in, const int* in_sizes, int n_in,
                              void* d_out, int out_size)
{
    const float* x    = (const float*)d_in[0];
    const float* Wxh  = (const float*)d_in[1];
    const float* Whh  = (const float*)d_in[2];
    const float* bias = (const float*)d_in[3];
    float* out = (float*)d_out;

    const int M = in_sizes[0] / DD;   // B*T

    dim3 gridA(M / BM, HH / BN);
    xp_gemm_kernel<<<gridA, 256>>>(x, Wxh, bias, out);

    rnn_rec_kernel<<<BATCH * 2, 256>>>(Whh, out);
}